// round 15
// baseline (speedup 1.0000x reference)
#include <cuda_runtime.h>
#include <cuda_bf16.h>
#include <mma.h>
#include <math.h>

using namespace nvcuda;

// ---------------------------------------------------------------------------
// GCN forward, 8 launches, HMMA (wmma bf16) GEMM1:
//   count(+W1->bf16) -> scan1(+fused scan2) -> scan3 -> convscatter
//   -> agg1 (bf16 t1) -> gemm1 [wmma bf16] -> agg2+pool -> final
// Self-cleaning graph replay (indeg zeroed in gemm1, pooled/cnti in final).
// NOTE: harness compiles PTX for compute_103 (no 'a') — tcgen05 unavailable.
// ---------------------------------------------------------------------------

#define MAXN 100000
#define MAXE 1600000
#define MAXG 64
#define MAXB ((MAXN + 4095) / 4096)

__device__ int   g_indeg[MAXN];
__device__ int   g_rowptr[MAXN + 1];
__device__ int   g_cursor[MAXN];
__device__ int   g_col[MAXE];
__device__ int   g_bsum[MAXB + 1];
__device__ int   g_cnti[MAXG];
__device__ float g_dinv[MAXN];
__device__ unsigned g_scan_done = 0;
__device__ __align__(16) __nv_bfloat16 g_xb[(size_t)MAXN * 64];
__device__ __align__(16) __nv_bfloat16 g_hb[(size_t)MAXN * 128];
__device__ __align__(16) __nv_bfloat16 g_t1b[(size_t)(MAXN + 128) * 64];
__device__ __align__(16) __nv_bfloat16 g_w1b[64 * 128];   // W1 bf16 [K=64][N=128]
__device__ float g_pooled[MAXG * 128];

// ---------------- count in-degree + convert W1 to bf16 [K][N] ----------------
__global__ void count_kernel(const int* __restrict__ ei,
                             const float* __restrict__ W1, int e) {
    int idx = blockIdx.x * blockDim.x + threadIdx.x;
    if (idx < e) atomicAdd(&g_indeg[ei[e + idx]], 1);
    if (idx < 4096) {                  // uint granularity: 2 consecutive bf16
        __nv_bfloat162 b = __floats2bfloat162_rn(W1[2 * idx], W1[2 * idx + 1]);
        ((unsigned*)g_w1b)[idx] = *reinterpret_cast<unsigned*>(&b);
    }
}

// ---------------- scan phase 1 + fused phase 2 (last-block pattern) ----------
__global__ void __launch_bounds__(256) scan1_kernel(int n) {
    __shared__ int sh[4096];
    __shared__ int wsum[8];
    __shared__ bool is_last;
    int t = threadIdx.x;
    int base = blockIdx.x * 4096;
#pragma unroll
    for (int j = 0; j < 16; j++) {
        int idx = base + t + j * 256;
        sh[t + j * 256] = (idx < n) ? g_indeg[idx] : 0;
    }
    __syncthreads();
    int v[16];
    int run = 0;
#pragma unroll
    for (int j = 0; j < 16; j++) { v[j] = run; run += sh[t * 16 + j]; }
    int lane = t & 31, w = t >> 5;
    int incl = run;
#pragma unroll
    for (int off = 1; off < 32; off <<= 1) {
        int tmp = __shfl_up_sync(0xffffffffu, incl, off);
        if (lane >= off) incl += tmp;
    }
    if (lane == 31) wsum[w] = incl;
    __syncthreads();
    if (t == 0) {
        int s = 0;
#pragma unroll
        for (int k = 0; k < 8; k++) { int x2 = wsum[k]; wsum[k] = s; s += x2; }
        g_bsum[blockIdx.x] = s;
    }
    __syncthreads();
    int texcl = wsum[w] + incl - run;
#pragma unroll
    for (int j = 0; j < 16; j++) sh[t * 16 + j] = texcl + v[j];
    __syncthreads();
#pragma unroll
    for (int j = 0; j < 16; j++) {
        int idx = base + t + j * 256;
        if (idx < n) g_rowptr[idx] = sh[t + j * 256];
    }
    __threadfence();
    if (t == 0) {
        unsigned ticket = atomicAdd(&g_scan_done, 1u);
        is_last = (ticket == gridDim.x - 1);
    }
    __syncthreads();
    if (is_last && t < 32) {
        int nb = gridDim.x;
        int x = (t < nb) ? g_bsum[t] : 0;
        int incl2 = x;
#pragma unroll
        for (int off = 1; off < 32; off <<= 1) {
            int tmp = __shfl_up_sync(0xffffffffu, incl2, off);
            if (t >= off) incl2 += tmp;
        }
        if (t < nb) g_bsum[t] = incl2 - x;
        int total = __shfl_sync(0xffffffffu, incl2, 31);
        if (t == 0) {
            g_rowptr[n] = total;
            g_scan_done = 0;
        }
    }
}

// -------- scan phase 3: offsets + dinv + cursor + graph counts -----------------
__global__ void scan3_kernel(const int* __restrict__ batch, int n) {
    int i = blockIdx.x * blockDim.x + threadIdx.x;
    if (i < n) {
        int r = g_rowptr[i] + g_bsum[i >> 12];
        g_rowptr[i] = r;
        g_cursor[i] = r;
        g_dinv[i] = rsqrtf((float)(g_indeg[i] + 1));
        atomicAdd(&g_cnti[batch[i]], 1);
    }
}

// -------- convert xb' = bf16(dinv*x) + scatter edges (merged) ------------------
__global__ void convscatter_kernel(const float* __restrict__ x,
                                   const int* __restrict__ ei,
                                   int nconv, int e) {
    int idx = blockIdx.x * blockDim.x + threadIdx.x;
    if (idx < nconv) {
        float d = g_dinv[idx >> 4];
        float4 v = ((const float4*)x)[idx];
        __nv_bfloat162 lo = __floats2bfloat162_rn(d * v.x, d * v.y);
        __nv_bfloat162 hi = __floats2bfloat162_rn(d * v.z, d * v.w);
        uint2 packed;
        packed.x = *reinterpret_cast<unsigned int*>(&lo);
        packed.y = *reinterpret_cast<unsigned int*>(&hi);
        ((uint2*)g_xb)[idx] = packed;
    }
    if (idx < e) {
        int s = ei[idx];
        int d = ei[e + idx];
        int pos = atomicAdd(&g_cursor[d], 1);
        g_col[pos] = s;
    }
}

// ---------------- agg1: t1b_i = bf16(di*(sum xb'_s + xb'_i)) ------------------
__global__ void agg1_kernel(int n) {
    int warp = (blockIdx.x * blockDim.x + threadIdx.x) >> 5;
    int lane = threadIdx.x & 31;
    if (warp >= n) return;
    int i = warp;
    const char* xb = (const char*)g_xb + lane * 4;
    int p0 = g_rowptr[i], p1 = g_rowptr[i + 1];
    float2 acc = make_float2(0.f, 0.f);
    int p = p0;
    while (p1 - p >= 16) {
        int myc = g_col[p + (lane & 15)];
#pragma unroll
        for (int j = 0; j < 16; j++) {
            unsigned o = (unsigned)__shfl_sync(0xffffffffu, myc, j) << 7;
            float2 v = __bfloat1622float2(*(const __nv_bfloat162*)(xb + o));
            acc.x += v.x; acc.y += v.y;
        }
        p += 16;
    }
    int rem = p1 - p;
    if (rem > 0) {
        int myc = g_col[p + (lane < rem ? lane : 0)];
        for (int j = 0; j < rem; j++) {
            unsigned o = (unsigned)__shfl_sync(0xffffffffu, myc, j) << 7;
            float2 v = __bfloat1622float2(*(const __nv_bfloat162*)(xb + o));
            acc.x += v.x; acc.y += v.y;
        }
    }
    float di = g_dinv[i];
    float2 xi = __bfloat1622float2(*(const __nv_bfloat162*)(xb + ((unsigned)i << 7)));
    __nv_bfloat162 r = __floats2bfloat162_rn(di * (acc.x + xi.x), di * (acc.y + xi.y));
    ((unsigned*)g_t1b)[(size_t)i * 32 + lane] = *reinterpret_cast<unsigned*>(&r);
}

// -------- GEMM1 via wmma bf16 HMMA: h = elu(t1b @ W1 + b1); hb'=bf16(dinv*h) --
// Block 256 threads = 8 warps; tile M=128 (16 rows/warp), N=128, K=64.
__global__ void __launch_bounds__(256) gemm1_wmma_kernel(const float* __restrict__ b1, int n) {
    __shared__ float hs[128 * 128];    // 64 KB result staging
    int tid = threadIdx.x;
    int wid = tid >> 5;
    int base = blockIdx.x * 128;
    int row0 = base + wid * 16;

    // self-clean for next replay: zero g_indeg (grid*256 >= n)
    int gid = blockIdx.x * 256 + tid;
    if (gid < n) g_indeg[gid] = 0;

    wmma::fragment<wmma::matrix_a, 16, 16, 16, __nv_bfloat16, wmma::row_major> af[4];
#pragma unroll
    for (int k = 0; k < 4; k++)
        wmma::load_matrix_sync(af[k], g_t1b + (size_t)row0 * 64 + k * 16, 64);

    wmma::fragment<wmma::accumulator, 16, 16, 16, float> cf[8];
#pragma unroll
    for (int nt = 0; nt < 8; nt++) wmma::fill_fragment(cf[nt], 0.0f);

    wmma::fragment<wmma::matrix_b, 16, 16, 16, __nv_bfloat16, wmma::row_major> bf;
#pragma unroll
    for (int k = 0; k < 4; k++) {
#pragma unroll
        for (int nt = 0; nt < 8; nt++) {
            wmma::load_matrix_sync(bf, g_w1b + k * 16 * 128 + nt * 16, 128);
            wmma::mma_sync(cf[nt], af[k], bf, cf[nt]);
        }
    }
#pragma unroll
    for (int nt = 0; nt < 8; nt++)
        wmma::store_matrix_sync(&hs[wid * 16 * 128 + nt * 16], cf[nt], 128,
                                wmma::mem_row_major);
    __syncthreads();

    // epilogue: thread handles row r = tid>>1, cols half*(64)
    int r = tid >> 1;
    int c0 = (tid & 1) * 64;
    int rowg = base + r;
    if (rowg < n) {
        float di = g_dinv[rowg];
        const float* src = &hs[r * 128 + c0];
        const float* bias = b1 + c0;
        unsigned outp[32];
#pragma unroll
        for (int c = 0; c < 32; c++) {
            float v0 = src[2 * c]     + bias[2 * c];
            float v1 = src[2 * c + 1] + bias[2 * c + 1];
            v0 = (v0 > 0.f) ? v0 : expm1f(v0);
            v1 = (v1 > 0.f) ? v1 : expm1f(v1);
            __nv_bfloat162 b = __floats2bfloat162_rn(di * v0, di * v1);
            outp[c] = *reinterpret_cast<unsigned*>(&b);
        }
        uint4* dst = (uint4*)(g_hb + (size_t)rowg * 128 + c0);
#pragma unroll
        for (int q = 0; q < 8; q++)
            dst[q] = make_uint4(outp[q * 4], outp[q * 4 + 1], outp[q * 4 + 2], outp[q * 4 + 3]);
    }
}

// -------- agg2 + mean-pool: shfl cols, pooled[g] += di*(sum hb'_s + hb'_i) ----
__device__ __forceinline__ float4 ld_h4o(const char* base, unsigned off) {
    uint2 raw = *(const uint2*)(base + off);
    __nv_bfloat162 b0 = *reinterpret_cast<__nv_bfloat162*>(&raw.x);
    __nv_bfloat162 b1 = *reinterpret_cast<__nv_bfloat162*>(&raw.y);
    float2 f0 = __bfloat1622float2(b0);
    float2 f1 = __bfloat1622float2(b1);
    return make_float4(f0.x, f0.y, f1.x, f1.y);
}

__global__ void __launch_bounds__(256) agg2_pool_kernel(const int* __restrict__ batch, int n) {
    __shared__ float ps[128];
    __shared__ int g0_s;
    int tid = threadIdx.x;
    int lane = tid & 31;
    int wid = tid >> 5;
    int node0 = blockIdx.x * 8;
    if (tid < 128) ps[tid] = 0.0f;
    if (tid == 0) g0_s = batch[node0 < n ? node0 : (n - 1)];
    __syncthreads();
    int g0 = g0_s;

    int i = node0 + wid;
    if (i < n) {
        const char* hb = (const char*)g_hb + lane * 8;
        int p0 = g_rowptr[i], p1 = g_rowptr[i + 1];
        float4 acc = make_float4(0.f, 0.f, 0.f, 0.f);
        int p = p0;
        while (p1 - p >= 16) {
            int myc = g_col[p + (lane & 15)];
#pragma unroll
            for (int j = 0; j < 16; j++) {
                unsigned o = (unsigned)__shfl_sync(0xffffffffu, myc, j) << 8;
                float4 v = ld_h4o(hb, o);
                acc.x += v.x; acc.y += v.y; acc.z += v.z; acc.w += v.w;
            }
            p += 16;
        }
        int rem = p1 - p;
        if (rem > 0) {
            int myc = g_col[p + (lane < rem ? lane : 0)];
            for (int j = 0; j < rem; j++) {
                unsigned o = (unsigned)__shfl_sync(0xffffffffu, myc, j) << 8;
                float4 v = ld_h4o(hb, o);
                acc.x += v.x; acc.y += v.y; acc.z += v.z; acc.w += v.w;
            }
        }
        float di = g_dinv[i];
        float4 hi = ld_h4o(hb, (unsigned)i << 8);
        float4 r;
        r.x = di * (acc.x + hi.x);
        r.y = di * (acc.y + hi.y);
        r.z = di * (acc.z + hi.z);
        r.w = di * (acc.w + hi.w);
        int g = batch[i];
        if (g == g0) {
            atomicAdd(&ps[lane * 4 + 0], r.x);
            atomicAdd(&ps[lane * 4 + 1], r.y);
            atomicAdd(&ps[lane * 4 + 2], r.z);
            atomicAdd(&ps[lane * 4 + 3], r.w);
        } else {
            float* pg = g_pooled + g * 128 + lane * 4;
            atomicAdd(pg + 0, r.x);
            atomicAdd(pg + 1, r.y);
            atomicAdd(pg + 2, r.z);
            atomicAdd(pg + 3, r.w);
        }
    }
    __syncthreads();
    if (tid < 128) atomicAdd(&g_pooled[g0 * 128 + tid], ps[tid]);
}

// ------- epilogue: W2 + MLP + log_softmax; zero pooled/cnti for next replay ---
__global__ void __launch_bounds__(128) final_kernel(
    const float* __restrict__ stats,
    const float* __restrict__ W2, const float* __restrict__ b2,
    const float* __restrict__ Wf1, const float* __restrict__ bf1,
    const float* __restrict__ Wf2, const float* __restrict__ bf2,
    float* __restrict__ out) {
    __shared__ float pm[128];
    __shared__ float zin[138];
    __shared__ float z1[20];
    __shared__ float z2[5];
    int g = blockIdx.x, t = threadIdx.x;
    float c = fmaxf((float)g_cnti[g], 1.0f);
    pm[t] = g_pooled[g * 128 + t] / c;
    g_pooled[g * 128 + t] = 0.0f;
    if (t == 0) g_cnti[g] = 0;
    __syncthreads();
    float acc = b2[t];
#pragma unroll 8
    for (int k = 0; k < 128; k++) acc = fmaf(pm[k], W2[k * 128 + t], acc);
    zin[t] = acc;
    if (t < 10) zin[128 + t] = stats[g * 10 + t];
    __syncthreads();
    if (t < 20) {
        float a = bf1[t];
        for (int k = 0; k < 138; k++) a = fmaf(zin[k], Wf1[k * 20 + t], a);
        z1[t] = fmaxf(a, 0.0f);
    }
    __syncthreads();
    if (t < 5) {
        float a = bf2[t];
        for (int k = 0; k < 20; k++) a = fmaf(z1[k], Wf2[k * 5 + t], a);
        z2[t] = a;
    }
    __syncthreads();
    if (t == 0) {
        float m = z2[0];
        for (int i = 1; i < 5; i++) m = fmaxf(m, z2[i]);
        float sum = 0.0f;
        for (int i = 0; i < 5; i++) sum += expf(z2[i] - m);
        float ls = m + logf(sum);
        for (int i = 0; i < 5; i++) out[g * 5 + i] = z2[i] - ls;
    }
}

// ---------------------------------------------------------------------------
extern "C" void kernel_launch(void* const* d_in, const int* in_sizes, int n_in,
                              void* d_out, int out_size) {
    const float* x     = (const float*)d_in[0];
    const int*   ei    = (const int*)d_in[1];
    const int*   batch = (const int*)d_in[2];
    const float* stats = (const float*)d_in[4];
    const float* W1    = (const float*)d_in[5];
    const float* b1    = (const float*)d_in[6];
    const float* W2    = (const float*)d_in[7];
    const float* b2    = (const float*)d_in[8];
    const float* Wf1   = (const float*)d_in[9];
    const float* bf1   = (const float*)d_in[10];
    const float* Wf2   = (const float*)d_in[11];
    const float* bf2   = (const float*)d_in[12];

    int n = in_sizes[0] / 64;
    int e = in_sizes[1] / 2;
    int G = in_sizes[4] / 10;
    int nb = (n + 4095) / 4096;
    int nconv = n * 16;
    int big = (nconv > e) ? nconv : e;

    count_kernel<<<(e + 255) / 256, 256>>>(ei, W1, e);
    scan1_kernel<<<nb, 256>>>(n);
    scan3_kernel<<<(n + 255) / 256, 256>>>(batch, n);
    convscatter_kernel<<<(big + 255) / 256, 256>>>(x, ei, nconv, e);
    agg1_kernel<<<(n * 32 + 255) / 256, 256>>>(n);
    gemm1_wmma_kernel<<<(n + 127) / 128, 256>>>(b1, n);
    agg2_pool_kernel<<<(n + 7) / 8, 256>>>(batch, n);
    final_kernel<<<G, 128>>>(stats, W2, b2, Wf1, bf1, Wf2, bf2, (float*)d_out);
}

// round 16
// speedup vs baseline: 1.0464x; 1.0464x over previous
#include <cuda_runtime.h>
#include <cuda_bf16.h>
#include <math.h>

// ---------------------------------------------------------------------------
// GCN forward, 8 launches (R13 structure, bf16 t1, f32x2 FFMA GEMM1):
//   count -> scan1(+fused scan2) -> scan3 -> convscatter
//   -> agg1 (bf16 t1b) -> gemm1 [f32x2 FFMA, bf16 A] -> agg2+pool -> final
// Self-cleaning graph replay (indeg zeroed in gemm1, pooled/cnti in final).
// NOTE: harness PTX target is compute_103 (no 'a') — tcgen05 unavailable.
// ---------------------------------------------------------------------------

#define MAXN 100000
#define MAXE 1600000
#define MAXG 64
#define MAXB ((MAXN + 4095) / 4096)

__device__ int   g_indeg[MAXN];
__device__ int   g_rowptr[MAXN + 1];
__device__ int   g_cursor[MAXN];
__device__ int   g_col[MAXE];
__device__ int   g_bsum[MAXB + 1];
__device__ int   g_cnti[MAXG];
__device__ float g_dinv[MAXN];
__device__ unsigned g_scan_done = 0;
__device__ __align__(16) __nv_bfloat16 g_xb[(size_t)MAXN * 64];
__device__ __align__(16) __nv_bfloat16 g_hb[(size_t)MAXN * 128];
__device__ __align__(16) __nv_bfloat16 g_t1b[(size_t)(MAXN + 128) * 64];
__device__ float g_pooled[MAXG * 128];

// ---------------- count in-degree --------------------------------------------
__global__ void count_kernel(const int* __restrict__ ei, int e) {
    int idx = blockIdx.x * blockDim.x + threadIdx.x;
    if (idx < e) atomicAdd(&g_indeg[ei[e + idx]], 1);
}

// ---------------- scan phase 1 + fused phase 2 (last-block pattern) ----------
__global__ void __launch_bounds__(256) scan1_kernel(int n) {
    __shared__ int sh[4096];
    __shared__ int wsum[8];
    __shared__ bool is_last;
    int t = threadIdx.x;
    int base = blockIdx.x * 4096;
#pragma unroll
    for (int j = 0; j < 16; j++) {
        int idx = base + t + j * 256;
        sh[t + j * 256] = (idx < n) ? g_indeg[idx] : 0;
    }
    __syncthreads();
    int v[16];
    int run = 0;
#pragma unroll
    for (int j = 0; j < 16; j++) { v[j] = run; run += sh[t * 16 + j]; }
    int lane = t & 31, w = t >> 5;
    int incl = run;
#pragma unroll
    for (int off = 1; off < 32; off <<= 1) {
        int tmp = __shfl_up_sync(0xffffffffu, incl, off);
        if (lane >= off) incl += tmp;
    }
    if (lane == 31) wsum[w] = incl;
    __syncthreads();
    if (t == 0) {
        int s = 0;
#pragma unroll
        for (int k = 0; k < 8; k++) { int x2 = wsum[k]; wsum[k] = s; s += x2; }
        g_bsum[blockIdx.x] = s;
    }
    __syncthreads();
    int texcl = wsum[w] + incl - run;
#pragma unroll
    for (int j = 0; j < 16; j++) sh[t * 16 + j] = texcl + v[j];
    __syncthreads();
#pragma unroll
    for (int j = 0; j < 16; j++) {
        int idx = base + t + j * 256;
        if (idx < n) g_rowptr[idx] = sh[t + j * 256];
    }
    __threadfence();
    if (t == 0) {
        unsigned ticket = atomicAdd(&g_scan_done, 1u);
        is_last = (ticket == gridDim.x - 1);
    }
    __syncthreads();
    if (is_last && t < 32) {
        int nb = gridDim.x;
        int x = (t < nb) ? g_bsum[t] : 0;
        int incl2 = x;
#pragma unroll
        for (int off = 1; off < 32; off <<= 1) {
            int tmp = __shfl_up_sync(0xffffffffu, incl2, off);
            if (t >= off) incl2 += tmp;
        }
        if (t < nb) g_bsum[t] = incl2 - x;
        int total = __shfl_sync(0xffffffffu, incl2, 31);
        if (t == 0) {
            g_rowptr[n] = total;
            g_scan_done = 0;
        }
    }
}

// -------- scan phase 3: offsets + dinv + cursor + graph counts -----------------
__global__ void scan3_kernel(const int* __restrict__ batch, int n) {
    int i = blockIdx.x * blockDim.x + threadIdx.x;
    if (i < n) {
        int r = g_rowptr[i] + g_bsum[i >> 12];
        g_rowptr[i] = r;
        g_cursor[i] = r;
        g_dinv[i] = rsqrtf((float)(g_indeg[i] + 1));
        atomicAdd(&g_cnti[batch[i]], 1);
    }
}

// -------- convert xb' = bf16(dinv*x) + scatter edges (merged) ------------------
__global__ void convscatter_kernel(const float* __restrict__ x,
                                   const int* __restrict__ ei,
                                   int nconv, int e) {
    int idx = blockIdx.x * blockDim.x + threadIdx.x;
    if (idx < nconv) {
        float d = g_dinv[idx >> 4];
        float4 v = ((const float4*)x)[idx];
        __nv_bfloat162 lo = __floats2bfloat162_rn(d * v.x, d * v.y);
        __nv_bfloat162 hi = __floats2bfloat162_rn(d * v.z, d * v.w);
        uint2 packed;
        packed.x = *reinterpret_cast<unsigned int*>(&lo);
        packed.y = *reinterpret_cast<unsigned int*>(&hi);
        ((uint2*)g_xb)[idx] = packed;
    }
    if (idx < e) {
        int s = ei[idx];
        int d = ei[e + idx];
        int pos = atomicAdd(&g_cursor[d], 1);
        g_col[pos] = s;
    }
}

// ---------------- agg1: t1b_i = bf16(di*(sum xb'_s + xb'_i)) ------------------
__global__ void agg1_kernel(int n) {
    int warp = (blockIdx.x * blockDim.x + threadIdx.x) >> 5;
    int lane = threadIdx.x & 31;
    if (warp >= n) return;
    int i = warp;
    const char* xb = (const char*)g_xb + lane * 4;
    int p0 = g_rowptr[i], p1 = g_rowptr[i + 1];
    float2 acc = make_float2(0.f, 0.f);
    int p = p0;
    while (p1 - p >= 16) {
        int myc = g_col[p + (lane & 15)];
#pragma unroll
        for (int j = 0; j < 16; j++) {
            unsigned o = (unsigned)__shfl_sync(0xffffffffu, myc, j) << 7;
            float2 v = __bfloat1622float2(*(const __nv_bfloat162*)(xb + o));
            acc.x += v.x; acc.y += v.y;
        }
        p += 16;
    }
    int rem = p1 - p;
    if (rem > 0) {
        int myc = g_col[p + (lane < rem ? lane : 0)];
        for (int j = 0; j < rem; j++) {
            unsigned o = (unsigned)__shfl_sync(0xffffffffu, myc, j) << 7;
            float2 v = __bfloat1622float2(*(const __nv_bfloat162*)(xb + o));
            acc.x += v.x; acc.y += v.y;
        }
    }
    float di = g_dinv[i];
    float2 xi = __bfloat1622float2(*(const __nv_bfloat162*)(xb + ((unsigned)i << 7)));
    __nv_bfloat162 r = __floats2bfloat162_rn(di * (acc.x + xi.x), di * (acc.y + xi.y));
    ((unsigned*)g_t1b)[(size_t)i * 32 + lane] = *reinterpret_cast<unsigned*>(&r);
}

// -------- GEMM1: h = elu(t1b @ W1 + b1), f32x2 FFMA, bf16 A, bf16 out ---------
__global__ void __launch_bounds__(256) gemm1_kernel(const float* __restrict__ W1,
                                                    const float* __restrict__ b1,
                                                    int n) {
    __shared__ float As[64 * 64];
    __shared__ float Ws[64 * 128];
    int tid = threadIdx.x;
    int base = blockIdx.x * 64;

    // self-clean for next replay: zero g_indeg (grid*256 >= n)
    int gid = blockIdx.x * 256 + tid;
    if (gid < n) g_indeg[gid] = 0;

    const float4* Wv = (const float4*)W1;
    float4* Wsv = (float4*)Ws;
#pragma unroll
    for (int i = 0; i < 8; i++) Wsv[tid + i * 256] = Wv[tid + i * 256];

    // load A: 64 rows x 32 bf16x2 = 2048 uints, convert to f32
    const unsigned* t1b = (const unsigned*)g_t1b;
#pragma unroll
    for (int j = 0; j < 8; j++) {
        int idx = tid + j * 256;            // 0..2047
        int row = idx >> 5, c = idx & 31;
        unsigned raw = t1b[(size_t)(base + row) * 32 + c];
        __nv_bfloat162 b = *reinterpret_cast<__nv_bfloat162*>(&raw);
        float2 f = __bfloat1622float2(b);
        As[row * 64 + 2 * c]     = f.x;
        As[row * 64 + 2 * c + 1] = f.y;
    }
    __syncthreads();

    int tx = tid & 31, ty = tid >> 5;
    int c0 = tx * 4, r0 = ty * 8;
    unsigned long long accp[8][2];
#pragma unroll
    for (int r = 0; r < 8; r++) { accp[r][0] = 0ull; accp[r][1] = 0ull; }

#pragma unroll 4
    for (int k = 0; k < 64; k++) {
        ulonglong2 bb = *(const ulonglong2*)(Ws + k * 128 + c0);
#pragma unroll
        for (int r = 0; r < 8; r++) {
            unsigned int au = __float_as_uint(As[(r0 + r) * 64 + k]);
            unsigned long long ap;
            asm("mov.b64 %0, {%1, %1};" : "=l"(ap) : "r"(au));
            asm("fma.rn.f32x2 %0, %1, %2, %0;" : "+l"(accp[r][0]) : "l"(ap), "l"(bb.x));
            asm("fma.rn.f32x2 %0, %1, %2, %0;" : "+l"(accp[r][1]) : "l"(ap), "l"(bb.y));
        }
    }

    float4 bias = *(const float4*)&b1[c0];
#pragma unroll
    for (int r = 0; r < 8; r++) {
        int row = base + r0 + r;
        if (row < n) {
            float di = g_dinv[row];
            unsigned int u0, u1, u2, u3;
            asm("mov.b64 {%0, %1}, %2;" : "=r"(u0), "=r"(u1) : "l"(accp[r][0]));
            asm("mov.b64 {%0, %1}, %2;" : "=r"(u2), "=r"(u3) : "l"(accp[r][1]));
            float4 o;
            o.x = __uint_as_float(u0) + bias.x;
            o.y = __uint_as_float(u1) + bias.y;
            o.z = __uint_as_float(u2) + bias.z;
            o.w = __uint_as_float(u3) + bias.w;
            o.x = (o.x > 0.f) ? o.x : expm1f(o.x);
            o.y = (o.y > 0.f) ? o.y : expm1f(o.y);
            o.z = (o.z > 0.f) ? o.z : expm1f(o.z);
            o.w = (o.w > 0.f) ? o.w : expm1f(o.w);
            __nv_bfloat162 lo = __floats2bfloat162_rn(di * o.x, di * o.y);
            __nv_bfloat162 hi = __floats2bfloat162_rn(di * o.z, di * o.w);
            uint2 packed;
            packed.x = *reinterpret_cast<unsigned int*>(&lo);
            packed.y = *reinterpret_cast<unsigned int*>(&hi);
            *(uint2*)(g_hb + (size_t)row * 128 + c0) = packed;
        }
    }
}

// -------- agg2 + mean-pool: 16 nodes/block, shfl cols -------------------------
__device__ __forceinline__ float4 ld_h4o(const char* base, unsigned off) {
    uint2 raw = *(const uint2*)(base + off);
    __nv_bfloat162 b0 = *reinterpret_cast<__nv_bfloat162*>(&raw.x);
    __nv_bfloat162 b1 = *reinterpret_cast<__nv_bfloat162*>(&raw.y);
    float2 f0 = __bfloat1622float2(b0);
    float2 f1 = __bfloat1622float2(b1);
    return make_float4(f0.x, f0.y, f1.x, f1.y);
}

__global__ void __launch_bounds__(512) agg2_pool_kernel(const int* __restrict__ batch, int n) {
    __shared__ float ps[128];
    __shared__ int g0_s;
    int tid = threadIdx.x;
    int lane = tid & 31;
    int wid = tid >> 5;                 // 0..15
    int node0 = blockIdx.x * 16;
    if (tid < 128) ps[tid] = 0.0f;
    if (tid == 0) g0_s = batch[node0 < n ? node0 : (n - 1)];
    __syncthreads();
    int g0 = g0_s;

    int i = node0 + wid;
    if (i < n) {
        const char* hb = (const char*)g_hb + lane * 8;
        int p0 = g_rowptr[i], p1 = g_rowptr[i + 1];
        float4 acc = make_float4(0.f, 0.f, 0.f, 0.f);
        int p = p0;
        while (p1 - p >= 16) {
            int myc = g_col[p + (lane & 15)];
#pragma unroll
            for (int j = 0; j < 16; j++) {
                unsigned o = (unsigned)__shfl_sync(0xffffffffu, myc, j) << 8;
                float4 v = ld_h4o(hb, o);
                acc.x += v.x; acc.y += v.y; acc.z += v.z; acc.w += v.w;
            }
            p += 16;
        }
        int rem = p1 - p;
        if (rem > 0) {
            int myc = g_col[p + (lane < rem ? lane : 0)];
            for (int j = 0; j < rem; j++) {
                unsigned o = (unsigned)__shfl_sync(0xffffffffu, myc, j) << 8;
                float4 v = ld_h4o(hb, o);
                acc.x += v.x; acc.y += v.y; acc.z += v.z; acc.w += v.w;
            }
        }
        float di = g_dinv[i];
        float4 hi = ld_h4o(hb, (unsigned)i << 8);
        float4 r;
        r.x = di * (acc.x + hi.x);
        r.y = di * (acc.y + hi.y);
        r.z = di * (acc.z + hi.z);
        r.w = di * (acc.w + hi.w);
        int g = batch[i];
        if (g == g0) {
            atomicAdd(&ps[lane * 4 + 0], r.x);
            atomicAdd(&ps[lane * 4 + 1], r.y);
            atomicAdd(&ps[lane * 4 + 2], r.z);
            atomicAdd(&ps[lane * 4 + 3], r.w);
        } else {
            float* pg = g_pooled + g * 128 + lane * 4;
            atomicAdd(pg + 0, r.x);
            atomicAdd(pg + 1, r.y);
            atomicAdd(pg + 2, r.z);
            atomicAdd(pg + 3, r.w);
        }
    }
    __syncthreads();
    if (tid < 128) atomicAdd(&g_pooled[g0 * 128 + tid], ps[tid]);
}

// ------- epilogue: W2 + MLP + log_softmax; zero pooled/cnti for next replay ---
__global__ void __launch_bounds__(128) final_kernel(
    const float* __restrict__ stats,
    const float* __restrict__ W2, const float* __restrict__ b2,
    const float* __restrict__ Wf1, const float* __restrict__ bf1,
    const float* __restrict__ Wf2, const float* __restrict__ bf2,
    float* __restrict__ out) {
    __shared__ float pm[128];
    __shared__ float zin[138];
    __shared__ float z1[20];
    __shared__ float z2[5];
    int g = blockIdx.x, t = threadIdx.x;
    float c = fmaxf((float)g_cnti[g], 1.0f);
    pm[t] = g_pooled[g * 128 + t] / c;
    g_pooled[g * 128 + t] = 0.0f;
    if (t == 0) g_cnti[g] = 0;
    __syncthreads();
    float acc = b2[t];
#pragma unroll 8
    for (int k = 0; k < 128; k++) acc = fmaf(pm[k], W2[k * 128 + t], acc);
    zin[t] = acc;
    if (t < 10) zin[128 + t] = stats[g * 10 + t];
    __syncthreads();
    if (t < 20) {
        float a = bf1[t];
        for (int k = 0; k < 138; k++) a = fmaf(zin[k], Wf1[k * 20 + t], a);
        z1[t] = fmaxf(a, 0.0f);
    }
    __syncthreads();
    if (t < 5) {
        float a = bf2[t];
        for (int k = 0; k < 20; k++) a = fmaf(z1[k], Wf2[k * 5 + t], a);
        z2[t] = a;
    }
    __syncthreads();
    if (t == 0) {
        float m = z2[0];
        for (int i = 1; i < 5; i++) m = fmaxf(m, z2[i]);
        float sum = 0.0f;
        for (int i = 0; i < 5; i++) sum += expf(z2[i] - m);
        float ls = m + logf(sum);
        for (int i = 0; i < 5; i++) out[g * 5 + i] = z2[i] - ls;
    }
}

// ---------------------------------------------------------------------------
extern "C" void kernel_launch(void* const* d_in, const int* in_sizes, int n_in,
                              void* d_out, int out_size) {
    const float* x     = (const float*)d_in[0];
    const int*   ei    = (const int*)d_in[1];
    const int*   batch = (const int*)d_in[2];
    const float* stats = (const float*)d_in[4];
    const float* W1    = (const float*)d_in[5];
    const float* b1    = (const float*)d_in[6];
    const float* W2    = (const float*)d_in[7];
    const float* b2    = (const float*)d_in[8];
    const float* Wf1   = (const float*)d_in[9];
    const float* bf1   = (const float*)d_in[10];
    const float* Wf2   = (const float*)d_in[11];
    const float* bf2   = (const float*)d_in[12];

    int n = in_sizes[0] / 64;
    int e = in_sizes[1] / 2;
    int G = in_sizes[4] / 10;
    int nb = (n + 4095) / 4096;
    int nconv = n * 16;
    int big = (nconv > e) ? nconv : e;

    count_kernel<<<(e + 255) / 256, 256>>>(ei, e);
    scan1_kernel<<<nb, 256>>>(n);
    scan3_kernel<<<(n + 255) / 256, 256>>>(batch, n);
    convscatter_kernel<<<(big + 255) / 256, 256>>>(x, ei, nconv, e);
    agg1_kernel<<<(n * 32 + 255) / 256, 256>>>(n);
    gemm1_kernel<<<(n + 63) / 64, 256>>>(W1, b1, n);
    agg2_pool_kernel<<<(n + 15) / 16, 512>>>(batch, n);
    final_kernel<<<G, 128>>>(stats, W2, b2, Wf1, bf1, Wf2, bf2, (float*)d_out);
}

// round 17
// speedup vs baseline: 1.0979x; 1.0492x over previous
#include <cuda_runtime.h>
#include <cuda_bf16.h>
#include <math.h>

// ---------------------------------------------------------------------------
// GCN forward, 8 launches (R13 structure + bf16 t1 into GEMM1):
//   count -> scan1(+fused scan2) -> scan3 -> convscatter
//   -> agg1 (bf16 t1b) -> gemm1 [f32x2 FFMA, bf16 A] -> agg2+pool (8/256) -> final
// Self-cleaning graph replay (indeg zeroed in gemm1, pooled/cnti in final).
// NOTE: harness PTX target is compute_103 (no 'a') — tcgen05 unavailable.
// ---------------------------------------------------------------------------

#define MAXN 100000
#define MAXE 1600000
#define MAXG 64
#define MAXB ((MAXN + 4095) / 4096)

__device__ int   g_indeg[MAXN];
__device__ int   g_rowptr[MAXN + 1];
__device__ int   g_cursor[MAXN];
__device__ int   g_col[MAXE];
__device__ int   g_bsum[MAXB + 1];
__device__ int   g_cnti[MAXG];
__device__ float g_dinv[MAXN];
__device__ unsigned g_scan_done = 0;
__device__ __align__(16) __nv_bfloat16 g_xb[(size_t)MAXN * 64];
__device__ __align__(16) __nv_bfloat16 g_hb[(size_t)MAXN * 128];
__device__ __align__(16) __nv_bfloat16 g_t1b[(size_t)(MAXN + 128) * 64];
__device__ float g_pooled[MAXG * 128];

// ---------------- count in-degree --------------------------------------------
__global__ void count_kernel(const int* __restrict__ ei, int e) {
    int idx = blockIdx.x * blockDim.x + threadIdx.x;
    if (idx < e) atomicAdd(&g_indeg[ei[e + idx]], 1);
}

// ---------------- scan phase 1 + fused phase 2 (last-block pattern) ----------
__global__ void __launch_bounds__(256) scan1_kernel(int n) {
    __shared__ int sh[4096];
    __shared__ int wsum[8];
    __shared__ bool is_last;
    int t = threadIdx.x;
    int base = blockIdx.x * 4096;
#pragma unroll
    for (int j = 0; j < 16; j++) {
        int idx = base + t + j * 256;
        sh[t + j * 256] = (idx < n) ? g_indeg[idx] : 0;
    }
    __syncthreads();
    int v[16];
    int run = 0;
#pragma unroll
    for (int j = 0; j < 16; j++) { v[j] = run; run += sh[t * 16 + j]; }
    int lane = t & 31, w = t >> 5;
    int incl = run;
#pragma unroll
    for (int off = 1; off < 32; off <<= 1) {
        int tmp = __shfl_up_sync(0xffffffffu, incl, off);
        if (lane >= off) incl += tmp;
    }
    if (lane == 31) wsum[w] = incl;
    __syncthreads();
    if (t == 0) {
        int s = 0;
#pragma unroll
        for (int k = 0; k < 8; k++) { int x2 = wsum[k]; wsum[k] = s; s += x2; }
        g_bsum[blockIdx.x] = s;
    }
    __syncthreads();
    int texcl = wsum[w] + incl - run;
#pragma unroll
    for (int j = 0; j < 16; j++) sh[t * 16 + j] = texcl + v[j];
    __syncthreads();
#pragma unroll
    for (int j = 0; j < 16; j++) {
        int idx = base + t + j * 256;
        if (idx < n) g_rowptr[idx] = sh[t + j * 256];
    }
    __threadfence();
    if (t == 0) {
        unsigned ticket = atomicAdd(&g_scan_done, 1u);
        is_last = (ticket == gridDim.x - 1);
    }
    __syncthreads();
    if (is_last && t < 32) {
        int nb = gridDim.x;
        int x = (t < nb) ? g_bsum[t] : 0;
        int incl2 = x;
#pragma unroll
        for (int off = 1; off < 32; off <<= 1) {
            int tmp = __shfl_up_sync(0xffffffffu, incl2, off);
            if (t >= off) incl2 += tmp;
        }
        if (t < nb) g_bsum[t] = incl2 - x;
        int total = __shfl_sync(0xffffffffu, incl2, 31);
        if (t == 0) {
            g_rowptr[n] = total;
            g_scan_done = 0;
        }
    }
}

// -------- scan phase 3: offsets + dinv + cursor + graph counts -----------------
__global__ void scan3_kernel(const int* __restrict__ batch, int n) {
    int i = blockIdx.x * blockDim.x + threadIdx.x;
    if (i < n) {
        int r = g_rowptr[i] + g_bsum[i >> 12];
        g_rowptr[i] = r;
        g_cursor[i] = r;
        g_dinv[i] = rsqrtf((float)(g_indeg[i] + 1));
        atomicAdd(&g_cnti[batch[i]], 1);
    }
}

// -------- convert xb' = bf16(dinv*x) + scatter edges (merged) ------------------
__global__ void convscatter_kernel(const float* __restrict__ x,
                                   const int* __restrict__ ei,
                                   int nconv, int e) {
    int idx = blockIdx.x * blockDim.x + threadIdx.x;
    if (idx < nconv) {
        float d = g_dinv[idx >> 4];
        float4 v = ((const float4*)x)[idx];
        __nv_bfloat162 lo = __floats2bfloat162_rn(d * v.x, d * v.y);
        __nv_bfloat162 hi = __floats2bfloat162_rn(d * v.z, d * v.w);
        uint2 packed;
        packed.x = *reinterpret_cast<unsigned int*>(&lo);
        packed.y = *reinterpret_cast<unsigned int*>(&hi);
        ((uint2*)g_xb)[idx] = packed;
    }
    if (idx < e) {
        int s = ei[idx];
        int d = ei[e + idx];
        int pos = atomicAdd(&g_cursor[d], 1);
        g_col[pos] = s;
    }
}

// ---------------- agg1: t1b_i = bf16(di*(sum xb'_s + xb'_i)) ------------------
__global__ void agg1_kernel(int n) {
    int warp = (blockIdx.x * blockDim.x + threadIdx.x) >> 5;
    int lane = threadIdx.x & 31;
    if (warp >= n) return;
    int i = warp;
    const char* xb = (const char*)g_xb + lane * 4;
    int p0 = g_rowptr[i], p1 = g_rowptr[i + 1];
    float2 acc = make_float2(0.f, 0.f);
    int p = p0;
    while (p1 - p >= 16) {
        int myc = g_col[p + (lane & 15)];
#pragma unroll
        for (int j = 0; j < 16; j++) {
            unsigned o = (unsigned)__shfl_sync(0xffffffffu, myc, j) << 7;
            float2 v = __bfloat1622float2(*(const __nv_bfloat162*)(xb + o));
            acc.x += v.x; acc.y += v.y;
        }
        p += 16;
    }
    int rem = p1 - p;
    if (rem > 0) {
        int myc = g_col[p + (lane < rem ? lane : 0)];
        for (int j = 0; j < rem; j++) {
            unsigned o = (unsigned)__shfl_sync(0xffffffffu, myc, j) << 7;
            float2 v = __bfloat1622float2(*(const __nv_bfloat162*)(xb + o));
            acc.x += v.x; acc.y += v.y;
        }
    }
    float di = g_dinv[i];
    float2 xi = __bfloat1622float2(*(const __nv_bfloat162*)(xb + ((unsigned)i << 7)));
    __nv_bfloat162 r = __floats2bfloat162_rn(di * (acc.x + xi.x), di * (acc.y + xi.y));
    ((unsigned*)g_t1b)[(size_t)i * 32 + lane] = *reinterpret_cast<unsigned*>(&r);
}

// -------- GEMM1: h = elu(t1b @ W1 + b1), f32x2 FFMA, bf16 A, bf16 out ---------
__global__ void __launch_bounds__(256) gemm1_kernel(const float* __restrict__ W1,
                                                    const float* __restrict__ b1,
                                                    int n) {
    __shared__ float As[64 * 64];
    __shared__ float Ws[64 * 128];
    int tid = threadIdx.x;
    int base = blockIdx.x * 64;

    // self-clean for next replay: zero g_indeg (grid*256 >= n)
    int gid = blockIdx.x * 256 + tid;
    if (gid < n) g_indeg[gid] = 0;

    const float4* Wv = (const float4*)W1;
    float4* Wsv = (float4*)Ws;
#pragma unroll
    for (int i = 0; i < 8; i++) Wsv[tid + i * 256] = Wv[tid + i * 256];

    // load A: 64 rows x 32 bf16x2 = 2048 uints, convert to f32
    const unsigned* t1b = (const unsigned*)g_t1b;
#pragma unroll
    for (int j = 0; j < 8; j++) {
        int idx = tid + j * 256;            // 0..2047
        int row = idx >> 5, c = idx & 31;
        unsigned raw = t1b[(size_t)(base + row) * 32 + c];
        __nv_bfloat162 b = *reinterpret_cast<__nv_bfloat162*>(&raw);
        float2 f = __bfloat1622float2(b);
        As[row * 64 + 2 * c]     = f.x;
        As[row * 64 + 2 * c + 1] = f.y;
    }
    __syncthreads();

    int tx = tid & 31, ty = tid >> 5;
    int c0 = tx * 4, r0 = ty * 8;
    unsigned long long accp[8][2];
#pragma unroll
    for (int r = 0; r < 8; r++) { accp[r][0] = 0ull; accp[r][1] = 0ull; }

#pragma unroll 4
    for (int k = 0; k < 64; k++) {
        ulonglong2 bb = *(const ulonglong2*)(Ws + k * 128 + c0);
#pragma unroll
        for (int r = 0; r < 8; r++) {
            unsigned int au = __float_as_uint(As[(r0 + r) * 64 + k]);
            unsigned long long ap;
            asm("mov.b64 %0, {%1, %1};" : "=l"(ap) : "r"(au));
            asm("fma.rn.f32x2 %0, %1, %2, %0;" : "+l"(accp[r][0]) : "l"(ap), "l"(bb.x));
            asm("fma.rn.f32x2 %0, %1, %2, %0;" : "+l"(accp[r][1]) : "l"(ap), "l"(bb.y));
        }
    }

    float4 bias = *(const float4*)&b1[c0];
#pragma unroll
    for (int r = 0; r < 8; r++) {
        int row = base + r0 + r;
        if (row < n) {
            float di = g_dinv[row];
            unsigned int u0, u1, u2, u3;
            asm("mov.b64 {%0, %1}, %2;" : "=r"(u0), "=r"(u1) : "l"(accp[r][0]));
            asm("mov.b64 {%0, %1}, %2;" : "=r"(u2), "=r"(u3) : "l"(accp[r][1]));
            float4 o;
            o.x = __uint_as_float(u0) + bias.x;
            o.y = __uint_as_float(u1) + bias.y;
            o.z = __uint_as_float(u2) + bias.z;
            o.w = __uint_as_float(u3) + bias.w;
            o.x = (o.x > 0.f) ? o.x : expm1f(o.x);
            o.y = (o.y > 0.f) ? o.y : expm1f(o.y);
            o.z = (o.z > 0.f) ? o.z : expm1f(o.z);
            o.w = (o.w > 0.f) ? o.w : expm1f(o.w);
            __nv_bfloat162 lo = __floats2bfloat162_rn(di * o.x, di * o.y);
            __nv_bfloat162 hi = __floats2bfloat162_rn(di * o.z, di * o.w);
            uint2 packed;
            packed.x = *reinterpret_cast<unsigned int*>(&lo);
            packed.y = *reinterpret_cast<unsigned int*>(&hi);
            *(uint2*)(g_hb + (size_t)row * 128 + c0) = packed;
        }
    }
}

// -------- agg2 + mean-pool: 8 nodes/block (256 thr), shfl cols ----------------
__device__ __forceinline__ float4 ld_h4o(const char* base, unsigned off) {
    uint2 raw = *(const uint2*)(base + off);
    __nv_bfloat162 b0 = *reinterpret_cast<__nv_bfloat162*>(&raw.x);
    __nv_bfloat162 b1 = *reinterpret_cast<__nv_bfloat162*>(&raw.y);
    float2 f0 = __bfloat1622float2(b0);
    float2 f1 = __bfloat1622float2(b1);
    return make_float4(f0.x, f0.y, f1.x, f1.y);
}

__global__ void __launch_bounds__(256) agg2_pool_kernel(const int* __restrict__ batch, int n) {
    __shared__ float ps[128];
    __shared__ int g0_s;
    int tid = threadIdx.x;
    int lane = tid & 31;
    int wid = tid >> 5;
    int node0 = blockIdx.x * 8;
    if (tid < 128) ps[tid] = 0.0f;
    if (tid == 0) g0_s = batch[node0 < n ? node0 : (n - 1)];
    __syncthreads();
    int g0 = g0_s;

    int i = node0 + wid;
    if (i < n) {
        const char* hb = (const char*)g_hb + lane * 8;
        int p0 = g_rowptr[i], p1 = g_rowptr[i + 1];
        float4 acc = make_float4(0.f, 0.f, 0.f, 0.f);
        int p = p0;
        while (p1 - p >= 16) {
            int myc = g_col[p + (lane & 15)];
#pragma unroll
            for (int j = 0; j < 16; j++) {
                unsigned o = (unsigned)__shfl_sync(0xffffffffu, myc, j) << 8;
                float4 v = ld_h4o(hb, o);
                acc.x += v.x; acc.y += v.y; acc.z += v.z; acc.w += v.w;
            }
            p += 16;
        }
        int rem = p1 - p;
        if (rem > 0) {
            int myc = g_col[p + (lane < rem ? lane : 0)];
            for (int j = 0; j < rem; j++) {
                unsigned o = (unsigned)__shfl_sync(0xffffffffu, myc, j) << 8;
                float4 v = ld_h4o(hb, o);
                acc.x += v.x; acc.y += v.y; acc.z += v.z; acc.w += v.w;
            }
        }
        float di = g_dinv[i];
        float4 hi = ld_h4o(hb, (unsigned)i << 8);
        float4 r;
        r.x = di * (acc.x + hi.x);
        r.y = di * (acc.y + hi.y);
        r.z = di * (acc.z + hi.z);
        r.w = di * (acc.w + hi.w);
        int g = batch[i];
        if (g == g0) {
            atomicAdd(&ps[lane * 4 + 0], r.x);
            atomicAdd(&ps[lane * 4 + 1], r.y);
            atomicAdd(&ps[lane * 4 + 2], r.z);
            atomicAdd(&ps[lane * 4 + 3], r.w);
        } else {
            float* pg = g_pooled + g * 128 + lane * 4;
            atomicAdd(pg + 0, r.x);
            atomicAdd(pg + 1, r.y);
            atomicAdd(pg + 2, r.z);
            atomicAdd(pg + 3, r.w);
        }
    }
    __syncthreads();
    if (tid < 128) atomicAdd(&g_pooled[g0 * 128 + tid], ps[tid]);
}

// ------- epilogue: W2 + MLP + log_softmax; zero pooled/cnti for next replay ---
__global__ void __launch_bounds__(128) final_kernel(
    const float* __restrict__ stats,
    const float* __restrict__ W2, const float* __restrict__ b2,
    const float* __restrict__ Wf1, const float* __restrict__ bf1,
    const float* __restrict__ Wf2, const float* __restrict__ bf2,
    float* __restrict__ out) {
    __shared__ float pm[128];
    __shared__ float zin[138];
    __shared__ float z1[20];
    __shared__ float z2[5];
    int g = blockIdx.x, t = threadIdx.x;
    float c = fmaxf((float)g_cnti[g], 1.0f);
    pm[t] = g_pooled[g * 128 + t] / c;
    g_pooled[g * 128 + t] = 0.0f;
    if (t == 0) g_cnti[g] = 0;
    __syncthreads();
    float acc = b2[t];
#pragma unroll 8
    for (int k = 0; k < 128; k++) acc = fmaf(pm[k], W2[k * 128 + t], acc);
    zin[t] = acc;
    if (t < 10) zin[128 + t] = stats[g * 10 + t];
    __syncthreads();
    if (t < 20) {
        float a = bf1[t];
        for (int k = 0; k < 138; k++) a = fmaf(zin[k], Wf1[k * 20 + t], a);
        z1[t] = fmaxf(a, 0.0f);
    }
    __syncthreads();
    if (t < 5) {
        float a = bf2[t];
        for (int k = 0; k < 20; k++) a = fmaf(z1[k], Wf2[k * 5 + t], a);
        z2[t] = a;
    }
    __syncthreads();
    if (t == 0) {
        float m = z2[0];
        for (int i = 1; i < 5; i++) m = fmaxf(m, z2[i]);
        float sum = 0.0f;
        for (int i = 0; i < 5; i++) sum += expf(z2[i] - m);
        float ls = m + logf(sum);
        for (int i = 0; i < 5; i++) out[g * 5 + i] = z2[i] - ls;
    }
}

// ---------------------------------------------------------------------------
extern "C" void kernel_launch(void* const* d_in, const int* in_sizes, int n_in,
                              void* d_out, int out_size) {
    const float* x     = (const float*)d_in[0];
    const int*   ei    = (const int*)d_in[1];
    const int*   batch = (const int*)d_in[2];
    const float* stats = (const float*)d_in[4];
    const float* W1    = (const float*)d_in[5];
    const float* b1    = (const float*)d_in[6];
    const float* W2    = (const float*)d_in[7];
    const float* b2    = (const float*)d_in[8];
    const float* Wf1   = (const float*)d_in[9];
    const float* bf1   = (const float*)d_in[10];
    const float* Wf2   = (const float*)d_in[11];
    const float* bf2   = (const float*)d_in[12];

    int n = in_sizes[0] / 64;
    int e = in_sizes[1] / 2;
    int G = in_sizes[4] / 10;
    int nb = (n + 4095) / 4096;
    int nconv = n * 16;
    int big = (nconv > e) ? nconv : e;

    count_kernel<<<(e + 255) / 256, 256>>>(ei, e);
    scan1_kernel<<<nb, 256>>>(n);
    scan3_kernel<<<(n + 255) / 256, 256>>>(batch, n);
    convscatter_kernel<<<(big + 255) / 256, 256>>>(x, ei, nconv, e);
    agg1_kernel<<<(n * 32 + 255) / 256, 256>>>(n);
    gemm1_kernel<<<(n + 63) / 64, 256>>>(W1, b1, n);
    agg2_pool_kernel<<<(n + 7) / 8, 256>>>(batch, n);
    final_kernel<<<G, 128>>>(stats, W2, b2, Wf1, bf1, Wf2, bf2, (float*)d_out);
}